// round 3
// baseline (speedup 1.0000x reference)
#include <cuda_runtime.h>

// ---------------------------------------------------------------------------
// SimpleRNN: 2-layer bidirectional tanh RNN + FC head.
//   B=32, T=2048, H=512, V=8192, out=1024.
// Pipeline (all fp32):
//   1) transpose Wih0 -> g_WihT [2][V][H]        (coalesced gather later)
//   2) gather: pre0[bt][dir*512+h] = WihT[dir][x][h] + bih0 + bhh0
//   3) recurrence layer0 (cluster-8 kernel, Whh SMEM-resident) -> g_hcat
//   4) GEMM: pre1 = hcat @ Wih1^T + bih1 + bhh1  (f32x2 packed FMA)
//   5) recurrence layer1 -> g_hcat
//   6) GEMM: out = hcat @ fcW^T + fcb
// ---------------------------------------------------------------------------

#define B_   32
#define T_   2048
#define H_   512
#define V_   8192
#define BT_  (B_ * T_)     // 65536
#define NW_  1024          // 2*H

// scratch (device globals; no allocations allowed)
__device__ float g_WihT[2 * V_ * H_];     //  33.5 MB
__device__ float g_pre [67108864];        // 268 MB  [BT][1024]
__device__ float g_hcat[67108864];        // 268 MB  [BT][1024]

// ---------------------------------------------------------------------------
// 1) Transpose Wih0 [2][H][V] -> g_WihT [2][V][H]
// ---------------------------------------------------------------------------
__global__ void transpose_k(const float* __restrict__ Wih0)
{
    __shared__ float tile[32][33];
    int d  = blockIdx.z;
    const float* S = Wih0   + (size_t)d * H_ * V_;
    float*       D = g_WihT + (size_t)d * V_ * H_;
    int v0 = blockIdx.x * 32;
    int h0 = blockIdx.y * 32;
    int tx = threadIdx.x, ty = threadIdx.y;
#pragma unroll
    for (int i = 0; i < 4; i++)
        tile[ty + 8 * i][tx] = S[(size_t)(h0 + ty + 8 * i) * V_ + v0 + tx];
    __syncthreads();
#pragma unroll
    for (int i = 0; i < 4; i++)
        D[(size_t)(v0 + ty + 8 * i) * H_ + h0 + tx] = tile[tx][ty + 8 * i];
}

// ---------------------------------------------------------------------------
// 2) Gather + biases -> g_pre (layer 0 pre-activations, layout [bt][1024])
// ---------------------------------------------------------------------------
__global__ void gather_k(const int* __restrict__ x,
                         const float* __restrict__ bih0,
                         const float* __restrict__ bhh0)
{
    int bt  = blockIdx.x;
    int idx = __ldg(&x[bt]);
    int o   = threadIdx.x * 4;          // 0..1020, stays inside one dir (512%4==0)
    int dir = o >> 9;
    int h   = o & 511;
    float4 w  = *(const float4*)&g_WihT[((size_t)dir * V_ + idx) * H_ + h];
    float4 b1 = *(const float4*)&bih0[o];
    float4 b2 = *(const float4*)&bhh0[o];
    float4 r;
    r.x = w.x + b1.x + b2.x;
    r.y = w.y + b1.y + b2.y;
    r.z = w.z + b1.z + b2.z;
    r.w = w.w + b1.w + b2.w;
    *(float4*)&g_pre[(size_t)bt * NW_ + o] = r;
}

// ---------------------------------------------------------------------------
// 3/5) Bidirectional recurrence, one layer.
// Grid = 128 CTAs = 16 clusters of 8. Cluster -> (dir, 4 batches).
// CTA rank r owns Whh rows [64r, 64r+64) resident in SMEM (padded to 516/row).
// Per step: every thread computes one h element, broadcasts it to all 8 CTAs'
// h-buffers via st.shared::cluster, then one cluster barrier.
// ---------------------------------------------------------------------------
#define RNN_WHH_FLOATS (64 * 516)
#define RNN_SMEM_BYTES ((RNN_WHH_FLOATS + 2 * 4 * H_) * 4)   // 148480

__global__ void __cluster_dims__(8, 1, 1) __launch_bounds__(256, 1)
rnn_layer_k(const float* __restrict__ Whh)
{
    extern __shared__ float sm[];
    float* whh  = sm;                        // [64][516]
    float* hbuf = sm + RNN_WHH_FLOATS;       // [2][4][512]

    int tid  = threadIdx.x;
    int bx   = blockIdx.x;
    int rank = bx & 7;                       // cluster rank (cluster dims (8,1,1))
    int cid  = bx >> 3;                      // 0..15
    int dir  = cid >> 3;                     // 0..1
    int b0   = (cid & 7) * 4;                // first batch of this cluster

    // load Whh slice (rows [64*rank, 64*rank+64))
    const float* W = Whh + (size_t)dir * H_ * H_ + (size_t)(rank * 64) * H_;
    for (int i = tid; i < 64 * H_; i += 256) {
        int r = i >> 9, k = i & 511;
        whh[r * 516 + k] = W[i];
    }
    for (int i = tid; i < 2 * 4 * H_; i += 256) hbuf[i] = 0.0f;
    __syncthreads();
    asm volatile("barrier.cluster.arrive.aligned;" ::: "memory");
    asm volatile("barrier.cluster.wait.aligned;" ::: "memory");

    int r    = tid & 63;
    int bl   = tid >> 6;                     // 0..3 local batch
    int grow = rank * 64 + r;                // global h row
    const float* wr = whh + r * 516;
    int colbase  = dir * H_ + grow;          // column in [bt][1024] layout
    int browbase = (b0 + bl) * T_;

    unsigned int hb_u32 = (unsigned int)__cvta_generic_to_shared(hbuf);

    int cur = 0;
    for (int t = 0; t < T_; t++) {
        int tt = dir ? (T_ - 1 - t) : t;
        int bt = browbase + tt;
        float pv = __ldg(&g_pre[(size_t)bt * NW_ + colbase]);   // hidden under k-loop

        const float* hb = hbuf + cur * (4 * H_) + bl * H_;
        float a0 = 0.f, a1 = 0.f, a2 = 0.f, a3 = 0.f;
#pragma unroll 16
        for (int k = 0; k < H_; k += 4) {
            float4 w  = *(const float4*)(wr + k);
            float4 h4 = *(const float4*)(hb + k);
            a0 = fmaf(w.x, h4.x, a0);
            a1 = fmaf(w.y, h4.y, a1);
            a2 = fmaf(w.z, h4.z, a2);
            a3 = fmaf(w.w, h4.w, a3);
        }
        float hn = tanhf(pv + ((a0 + a1) + (a2 + a3)));

        g_hcat[(size_t)bt * NW_ + colbase] = hn;

        // broadcast hn into every cluster CTA's next h-buffer
        int nxt = cur ^ 1;
        unsigned int laddr = hb_u32 +
            (unsigned int)((nxt * 4 * H_ + bl * H_ + grow) * 4);
#pragma unroll
        for (int p = 0; p < 8; p++) {
            unsigned int ra;
            asm volatile("mapa.shared::cluster.u32 %0, %1, %2;"
                         : "=r"(ra) : "r"(laddr), "r"(p));
            asm volatile("st.shared::cluster.f32 [%0], %1;"
                         :: "r"(ra), "f"(hn) : "memory");
        }
        asm volatile("barrier.cluster.arrive.aligned;" ::: "memory");
        asm volatile("barrier.cluster.wait.aligned;" ::: "memory");
        cur = nxt;
    }
}

// ---------------------------------------------------------------------------
// 4/6) C[bt][n] = sum_k g_hcat[bt][k] * Bw[n][k] + bias1[n] (+ bias2[n])
// M=65536, N=1024, K=1024. BM=128, BN=64, BK=16, 256 thr, 8x4 microtile,
// packed f32x2 FMA along M (2 MACs/lane/instr).
// ---------------------------------------------------------------------------
#define FMA2(d, a, b) \
    asm("fma.rn.f32x2 %0, %1, %2, %0;" : "+l"(d) : "l"(a), "l"(b))

__global__ __launch_bounds__(256)
void gemm_k(const float* __restrict__ Bw,
            const float* __restrict__ bias1,
            const float* __restrict__ bias2,
            float* __restrict__ Cext,
            int use_pre)
{
    __shared__ float As[16 * 130];   // [k][m], pad 130 -> conflict-free stores
    __shared__ float Bs[16 * 68];    // [k][n], pad 68

    float* C = use_pre ? g_pre : Cext;
    const int K = 1024;
    int m0 = blockIdx.y * 128;
    int n0 = blockIdx.x * 64;
    int tid = threadIdx.x;
    int tx = tid & 15;               // n-group: cols n0 + tx*4 .. +4
    int ty = tid >> 4;               // m-group: rows m0 + ty*8 .. +8

    unsigned long long acc[4][4];    // [m-pair][n] packed f32x2
#pragma unroll
    for (int i = 0; i < 4; i++)
#pragma unroll
        for (int j = 0; j < 4; j++) acc[i][j] = 0ULL;

    for (int kt = 0; kt < K; kt += 16) {
        // A tile: 128 rows x 16 k (512 float4, 2 per thread), store transposed
#pragma unroll
        for (int i = 0; i < 2; i++) {
            int j  = tid + 256 * i;
            int m  = j >> 2, kq = j & 3;
            float4 v = *(const float4*)&g_hcat[(size_t)(m0 + m) * 1024 + kt + kq * 4];
            As[(kq * 4 + 0) * 130 + m] = v.x;
            As[(kq * 4 + 1) * 130 + m] = v.y;
            As[(kq * 4 + 2) * 130 + m] = v.z;
            As[(kq * 4 + 3) * 130 + m] = v.w;
        }
        // B tile: 64 rows x 16 k (256 float4, 1 per thread)
        {
            int n = tid >> 2, kq = tid & 3;
            float4 v = *(const float4*)&Bw[(size_t)(n0 + n) * 1024 + kt + kq * 4];
            Bs[(kq * 4 + 0) * 68 + n] = v.x;
            Bs[(kq * 4 + 1) * 68 + n] = v.y;
            Bs[(kq * 4 + 2) * 68 + n] = v.z;
            Bs[(kq * 4 + 3) * 68 + n] = v.w;
        }
        __syncthreads();

#pragma unroll
        for (int k = 0; k < 16; k++) {
            const unsigned long long* ap =
                (const unsigned long long*)(As + k * 130 + ty * 8);
            unsigned long long a[4];
            a[0] = ap[0]; a[1] = ap[1]; a[2] = ap[2]; a[3] = ap[3];
            float4 bv = *(const float4*)(Bs + k * 68 + tx * 4);
            unsigned long long b[4];
            asm("mov.b64 %0, {%1, %1};" : "=l"(b[0]) : "f"(bv.x));
            asm("mov.b64 %0, {%1, %1};" : "=l"(b[1]) : "f"(bv.y));
            asm("mov.b64 %0, {%1, %1};" : "=l"(b[2]) : "f"(bv.z));
            asm("mov.b64 %0, {%1, %1};" : "=l"(b[3]) : "f"(bv.w));
#pragma unroll
            for (int i = 0; i < 4; i++)
#pragma unroll
                for (int j = 0; j < 4; j++)
                    FMA2(acc[i][j], a[i], b[j]);
        }
        __syncthreads();
    }

    // epilogue: unpack, add biases, store
    float bs[4];
#pragma unroll
    for (int j = 0; j < 4; j++) {
        int n = n0 + tx * 4 + j;
        bs[j] = bias1[n] + (bias2 ? bias2[n] : 0.0f);
    }
#pragma unroll
    for (int i = 0; i < 4; i++) {
        float lo[4], hi[4];
#pragma unroll
        for (int j = 0; j < 4; j++) {
            float l, h;
            asm("mov.b64 {%0, %1}, %2;" : "=f"(l), "=f"(h) : "l"(acc[i][j]));
            lo[j] = l; hi[j] = h;
        }
        int mA = m0 + ty * 8 + 2 * i;
        float4 r0, r1;
        r0.x = lo[0] + bs[0]; r0.y = lo[1] + bs[1];
        r0.z = lo[2] + bs[2]; r0.w = lo[3] + bs[3];
        r1.x = hi[0] + bs[0]; r1.y = hi[1] + bs[1];
        r1.z = hi[2] + bs[2]; r1.w = hi[3] + bs[3];
        *(float4*)&C[(size_t)mA * 1024 + n0 + tx * 4]       = r0;
        *(float4*)&C[(size_t)(mA + 1) * 1024 + n0 + tx * 4] = r1;
    }
}

// ---------------------------------------------------------------------------
extern "C" void kernel_launch(void* const* d_in, const int* in_sizes, int n_in,
                              void* d_out, int out_size)
{
    const int*   x    = (const int*)  d_in[0];
    const float* Wih0 = (const float*)d_in[1];
    const float* Whh0 = (const float*)d_in[2];
    const float* bih0 = (const float*)d_in[3];
    const float* bhh0 = (const float*)d_in[4];
    const float* Wih1 = (const float*)d_in[5];
    const float* Whh1 = (const float*)d_in[6];
    const float* bih1 = (const float*)d_in[7];
    const float* bhh1 = (const float*)d_in[8];
    const float* fcW  = (const float*)d_in[9];
    const float* fcb  = (const float*)d_in[10];
    float* out = (float*)d_out;

    cudaFuncSetAttribute(rnn_layer_k,
                         cudaFuncAttributeMaxDynamicSharedMemorySize,
                         RNN_SMEM_BYTES);

    transpose_k<<<dim3(V_ / 32, H_ / 32, 2), dim3(32, 8)>>>(Wih0);
    gather_k<<<BT_, 256>>>(x, bih0, bhh0);
    rnn_layer_k<<<128, 256, RNN_SMEM_BYTES>>>(Whh0);
    gemm_k<<<dim3(16, BT_ / 128), 256>>>(Wih1, bih1, bhh1, nullptr, 1);
    rnn_layer_k<<<128, 256, RNN_SMEM_BYTES>>>(Whh1);
    gemm_k<<<dim3(16, BT_ / 128), 256>>>(fcW, fcb, nullptr, out, 0);
}

// round 5
// speedup vs baseline: 1.2507x; 1.2507x over previous
#include <cuda_runtime.h>

// ---------------------------------------------------------------------------
// SimpleRNN: 2-layer bidirectional tanh RNN + FC head.  B=32,T=2048,H=512.
//  - recurrence: Whh register-resident (128 regs/thread), fma.f32x2 packed
//    along k, h broadcast across 8-CTA cluster via st.async + mbarrier.
//  - GEMMs: 128x128x16 tiles, f32x2 packed FMA along M.
// ---------------------------------------------------------------------------

#define B_   32
#define T_   2048
#define H_   512
#define V_   8192
#define BT_  (B_ * T_)     // 65536
#define NW_  1024          // 2*H

__device__ float g_WihT[2 * V_ * H_];     //  33.5 MB
__device__ float g_pre [67108864];        // 268 MB  [BT][1024]
__device__ float g_hcat[67108864];        // 268 MB  [BT][1024]

// ---------------------------------------------------------------------------
// 1) Transpose Wih0 [2][H][V] -> g_WihT [2][V][H]
// ---------------------------------------------------------------------------
__global__ void transpose_k(const float* __restrict__ Wih0)
{
    __shared__ float tile[32][33];
    int d  = blockIdx.z;
    const float* S = Wih0   + (size_t)d * H_ * V_;
    float*       D = g_WihT + (size_t)d * V_ * H_;
    int v0 = blockIdx.x * 32;
    int h0 = blockIdx.y * 32;
    int tx = threadIdx.x, ty = threadIdx.y;
#pragma unroll
    for (int i = 0; i < 4; i++)
        tile[ty + 8 * i][tx] = S[(size_t)(h0 + ty + 8 * i) * V_ + v0 + tx];
    __syncthreads();
#pragma unroll
    for (int i = 0; i < 4; i++)
        D[(size_t)(v0 + ty + 8 * i) * H_ + h0 + tx] = tile[tx][ty + 8 * i];
}

// ---------------------------------------------------------------------------
// 2) Gather + biases -> g_pre
// ---------------------------------------------------------------------------
__global__ void gather_k(const int* __restrict__ x,
                         const float* __restrict__ bih0,
                         const float* __restrict__ bhh0)
{
    int bt  = blockIdx.x;
    int idx = __ldg(&x[bt]);
    int o   = threadIdx.x * 4;
    int dir = o >> 9;
    int h   = o & 511;
    float4 w  = *(const float4*)&g_WihT[((size_t)dir * V_ + idx) * H_ + h];
    float4 b1 = *(const float4*)&bih0[o];
    float4 b2 = *(const float4*)&bhh0[o];
    float4 r;
    r.x = w.x + b1.x + b2.x;
    r.y = w.y + b1.y + b2.y;
    r.z = w.z + b1.z + b2.z;
    r.w = w.w + b1.w + b2.w;
    *(float4*)&g_pre[(size_t)bt * NW_ + o] = r;
}

// ---------------------------------------------------------------------------
// 3/5) Recurrence. 16 clusters x 8 CTAs. CTA rank owns 64 Whh rows in REGS.
// Thread (r = tid>>2, kq = tid&3): w[grow][kq*128 .. +128) in 64 u64 regs,
// computes partial dots for 4 batches, shuffle-reduce over kq, lane handles
// batch b=kq, broadcasts h via st.async to all 8 CTAs, mbarrier sync.
// ---------------------------------------------------------------------------
#define FMA2(d, a, b) \
    asm("fma.rn.f32x2 %0, %1, %2, %0;" : "+l"(d) : "l"(a), "l"(b))

#define HB_WORDS 2112                    // 4 batches * (4 chunks * 132)
#define HB_BYTES (HB_WORDS * 4)          // 8448 per buffer

__global__ void __cluster_dims__(8, 1, 1) __launch_bounds__(256, 1)
rnn_layer_k(const float* __restrict__ Whh)
{
    __shared__ __align__(16) float s_h[2][4][528];   // [buf][batch][4 chunks * 132]
    __shared__ __align__(8)  unsigned long long s_mbar[2];

    int tid  = threadIdx.x;
    int rank = blockIdx.x & 7;
    int cid  = blockIdx.x >> 3;
    int dir  = cid >> 3;
    int b0   = (cid & 7) * 4;

    int kq   = tid & 3;                  // k-chunk 0..3 (lane bits 0-1)
    int r    = tid >> 2;                 // 0..63
    int grow = rank * 64 + r;
    int colbase = dir * H_ + grow;

    // --- load my 128-float w chunk into registers (64 packed u64) ---
    unsigned long long wp[64];
    const unsigned long long* Wrow = (const unsigned long long*)
        (Whh + ((size_t)dir * H_ + grow) * H_ + kq * 128);
#pragma unroll
    for (int i = 0; i < 64; i++) wp[i] = Wrow[i];

    // --- init buffer 0 (h_{-1}=0) and mbarriers ---
    for (int i = tid; i < HB_WORDS; i += 256) ((float*)s_h[0])[i] = 0.0f;
    unsigned int hbase = (unsigned int)__cvta_generic_to_shared(&s_h[0][0][0]);
    unsigned int mbase = (unsigned int)__cvta_generic_to_shared(&s_mbar[0]);
    if (tid == 0) {
        asm volatile("mbarrier.init.shared.b64 [%0], %1;" :: "r"(mbase),     "r"(1) : "memory");
        asm volatile("mbarrier.init.shared.b64 [%0], %1;" :: "r"(mbase + 8), "r"(1) : "memory");
    }
    __syncthreads();
    asm volatile("barrier.cluster.arrive.aligned;" ::: "memory");
    asm volatile("barrier.cluster.wait.aligned;" ::: "memory");

    // peer SMEM base addresses (cluster window)
    unsigned int peer[8];
    unsigned int mdelta = mbase - hbase;
#pragma unroll
    for (int p = 0; p < 8; p++)
        asm volatile("mapa.shared::cluster.u32 %0, %1, %2;"
                     : "=r"(peer[p]) : "r"(hbase), "r"(p));

    // my output slot (byte offset within an h-buffer):
    // batch = kq, chunk = grow>>7 (== rank>>1), elem = grow & 127
    unsigned int slot = (unsigned int)((kq * 528 + (rank >> 1) * 132 + (grow & 127)) * 4);

    size_t brow = (size_t)(b0 + kq) * T_;
    float pv = __ldg(&g_pre[((brow + (dir ? (T_ - 1) : 0)) << 10) + colbase]);

    for (int t = 0; t < T_; t++) {
        int cur = t & 1;
        int nxt = cur ^ 1;

        // ---- partial dot products (w in regs, h broadcast from smem) ----
        // hp in 16-byte units; one batch = 528 floats = 132 ulonglong2.
        const ulonglong2* hp = (const ulonglong2*)&s_h[cur][0][kq * 132];
        unsigned long long a0 = 0ULL, a1 = 0ULL, a2 = 0ULL, a3 = 0ULL;
#pragma unroll
        for (int i = 0; i < 32; i++) {
            ulonglong2 x0 = hp[i];         // batch 0
            ulonglong2 y1 = hp[132 + i];   // batch 1
            ulonglong2 y2 = hp[264 + i];   // batch 2
            ulonglong2 y3 = hp[396 + i];   // batch 3
            FMA2(a0, wp[2 * i], x0.x); FMA2(a0, wp[2 * i + 1], x0.y);
            FMA2(a1, wp[2 * i], y1.x); FMA2(a1, wp[2 * i + 1], y1.y);
            FMA2(a2, wp[2 * i], y2.x); FMA2(a2, wp[2 * i + 1], y2.y);
            FMA2(a3, wp[2 * i], y3.x); FMA2(a3, wp[2 * i + 1], y3.y);
        }
        float s0, s1, s2, s3;
        {
            float lo, hi;
            asm("mov.b64 {%0, %1}, %2;" : "=f"(lo), "=f"(hi) : "l"(a0)); s0 = lo + hi;
            asm("mov.b64 {%0, %1}, %2;" : "=f"(lo), "=f"(hi) : "l"(a1)); s1 = lo + hi;
            asm("mov.b64 {%0, %1}, %2;" : "=f"(lo), "=f"(hi) : "l"(a2)); s2 = lo + hi;
            asm("mov.b64 {%0, %1}, %2;" : "=f"(lo), "=f"(hi) : "l"(a3)); s3 = lo + hi;
        }
        // reduce across the 4 kq lanes (lane bits 0-1)
        s0 += __shfl_xor_sync(0xffffffffu, s0, 1);
        s1 += __shfl_xor_sync(0xffffffffu, s1, 1);
        s2 += __shfl_xor_sync(0xffffffffu, s2, 1);
        s3 += __shfl_xor_sync(0xffffffffu, s3, 1);
        s0 += __shfl_xor_sync(0xffffffffu, s0, 2);
        s1 += __shfl_xor_sync(0xffffffffu, s1, 2);
        s2 += __shfl_xor_sync(0xffffffffu, s2, 2);
        s3 += __shfl_xor_sync(0xffffffffu, s3, 2);
        float sel = (kq & 2) ? ((kq & 1) ? s3 : s2) : ((kq & 1) ? s1 : s0);

        __syncthreads();   // all reads of buf[cur] done before refills begin

        if (tid == 0 && t < T_ - 1)
            asm volatile("mbarrier.arrive.expect_tx.shared.b64 _, [%0], %1;"
                         :: "r"(mbase + (unsigned)(nxt * 8)), "r"(8192) : "memory");

        float hn = tanhf(pv + sel);
        int tt = dir ? (T_ - 1 - t) : t;
        g_hcat[((brow + tt) << 10) + colbase] = hn;

        if (t < T_ - 1) {
            unsigned int v   = __float_as_uint(hn);
            unsigned int off = (unsigned)(nxt * HB_BYTES) + slot;
#pragma unroll
            for (int p = 0; p < 8; p++) {
                unsigned int da = peer[p] + off;
                unsigned int mb = peer[p] + mdelta + (unsigned)(nxt * 8);
                asm volatile(
                    "st.async.shared::cluster.mbarrier::complete_tx::bytes.b32 [%0], %1, [%2];"
                    :: "r"(da), "r"(v), "r"(mb) : "memory");
            }
            int tn = dir ? (T_ - 2 - t) : (t + 1);
            pv = __ldg(&g_pre[((brow + tn) << 10) + colbase]);

            // wait for full h of next step
            unsigned int mb  = mbase + (unsigned)(nxt * 8);
            unsigned int par = (unsigned)((t >> 1) & 1);
            unsigned int done;
            asm volatile(
                "{\n\t.reg .pred p;\n\t"
                "mbarrier.try_wait.parity.acquire.cta.shared::cta.b64 p, [%1], %2;\n\t"
                "selp.b32 %0, 1, 0, p;\n\t}"
                : "=r"(done) : "r"(mb), "r"(par) : "memory");
            if (!done) {
                asm volatile(
                    "{\n\t.reg .pred P1;\n\t"
                    "WL_%=:\n\t"
                    "mbarrier.try_wait.parity.acquire.cta.shared::cta.b64 P1, [%0], %1, 0x989680;\n\t"
                    "@P1 bra.uni WD_%=;\n\t"
                    "bra.uni WL_%=;\n\t"
                    "WD_%=:\n\t}"
                    :: "r"(mb), "r"(par) : "memory");
            }
        }
    }
}

// ---------------------------------------------------------------------------
// 4/6) C[m][n] = sum_k g_hcat[m][k] * Bw[n][k] + bias1[n] (+ bias2[n])
// M=65536, N=1024, K=1024. BM=128, BN=128, BK=16, 256 thr, 8x8 microtile,
// f32x2 packed along M.
// ---------------------------------------------------------------------------
__global__ __launch_bounds__(256)
void gemm_k(const float* __restrict__ Bw,
            const float* __restrict__ bias1,
            const float* __restrict__ bias2,
            float* __restrict__ Cext,
            int use_pre)
{
    __shared__ __align__(16) float As[16 * 132];   // [k][m]
    __shared__ __align__(16) float Bs[16 * 132];   // [k][n]

    float* C = use_pre ? g_pre : Cext;
    int m0 = blockIdx.y * 128;
    int n0 = blockIdx.x * 128;
    int tid = threadIdx.x;
    int tx = tid & 15;               // n-group: cols n0 + tx*8 .. +8
    int ty = tid >> 4;               // m-group: rows m0 + ty*8 .. +8

    unsigned long long acc[4][8];
#pragma unroll
    for (int i = 0; i < 4; i++)
#pragma unroll
        for (int j = 0; j < 8; j++) acc[i][j] = 0ULL;

    for (int kt = 0; kt < 1024; kt += 16) {
#pragma unroll
        for (int i = 0; i < 2; i++) {
            int j  = tid + 256 * i;
            int m  = j >> 2, kk = j & 3;
            float4 va = *(const float4*)&g_hcat[(size_t)(m0 + m) * 1024 + kt + kk * 4];
            As[(kk * 4 + 0) * 132 + m] = va.x;
            As[(kk * 4 + 1) * 132 + m] = va.y;
            As[(kk * 4 + 2) * 132 + m] = va.z;
            As[(kk * 4 + 3) * 132 + m] = va.w;
            float4 vb = *(const float4*)&Bw[(size_t)(n0 + m) * 1024 + kt + kk * 4];
            Bs[(kk * 4 + 0) * 132 + m] = vb.x;
            Bs[(kk * 4 + 1) * 132 + m] = vb.y;
            Bs[(kk * 4 + 2) * 132 + m] = vb.z;
            Bs[(kk * 4 + 3) * 132 + m] = vb.w;
        }
        __syncthreads();

#pragma unroll
        for (int k = 0; k < 16; k++) {
            const ulonglong2* ap = (const ulonglong2*)(As + k * 132 + ty * 8);
            ulonglong2 av0 = ap[0], av1 = ap[1];
            unsigned long long a[4] = {av0.x, av0.y, av1.x, av1.y};
            float4 bv0 = *(const float4*)(Bs + k * 132 + tx * 8);
            float4 bv1 = *(const float4*)(Bs + k * 132 + tx * 8 + 4);
            unsigned long long b[8];
            asm("mov.b64 %0, {%1, %1};" : "=l"(b[0]) : "f"(bv0.x));
            asm("mov.b64 %0, {%1, %1};" : "=l"(b[1]) : "f"(bv0.y));
            asm("mov.b64 %0, {%1, %1};" : "=l"(b[2]) : "f"(bv0.z));
            asm("mov.b64 %0, {%1, %1};" : "=l"(b[3]) : "f"(bv0.w));
            asm("mov.b64 %0, {%1, %1};" : "=l"(b[4]) : "f"(bv1.x));
            asm("mov.b64 %0, {%1, %1};" : "=l"(b[5]) : "f"(bv1.y));
            asm("mov.b64 %0, {%1, %1};" : "=l"(b[6]) : "f"(bv1.z));
            asm("mov.b64 %0, {%1, %1};" : "=l"(b[7]) : "f"(bv1.w));
#pragma unroll
            for (int i = 0; i < 4; i++)
#pragma unroll
                for (int j = 0; j < 8; j++)
                    FMA2(acc[i][j], a[i], b[j]);
        }
        __syncthreads();
    }

    float bs[8];
#pragma unroll
    for (int j = 0; j < 8; j++) {
        int n = n0 + tx * 8 + j;
        bs[j] = bias1[n] + (bias2 ? bias2[n] : 0.0f);
    }
#pragma unroll
    for (int i = 0; i < 4; i++) {
        float lo[8], hi[8];
#pragma unroll
        for (int j = 0; j < 8; j++) {
            float l, h;
            asm("mov.b64 {%0, %1}, %2;" : "=f"(l), "=f"(h) : "l"(acc[i][j]));
            lo[j] = l; hi[j] = h;
        }
        size_t row0 = (size_t)(m0 + ty * 8 + 2 * i) * 1024 + n0 + tx * 8;
        float4 r0, r1, r2, r3;
        r0.x = lo[0] + bs[0]; r0.y = lo[1] + bs[1]; r0.z = lo[2] + bs[2]; r0.w = lo[3] + bs[3];
        r1.x = lo[4] + bs[4]; r1.y = lo[5] + bs[5]; r1.z = lo[6] + bs[6]; r1.w = lo[7] + bs[7];
        r2.x = hi[0] + bs[0]; r2.y = hi[1] + bs[1]; r2.z = hi[2] + bs[2]; r2.w = hi[3] + bs[3];
        r3.x = hi[4] + bs[4]; r3.y = hi[5] + bs[5]; r3.z = hi[6] + bs[6]; r3.w = hi[7] + bs[7];
        *(float4*)&C[row0]            = r0;
        *(float4*)&C[row0 + 4]        = r1;
        *(float4*)&C[row0 + 1024]     = r2;
        *(float4*)&C[row0 + 1024 + 4] = r3;
    }
}

// ---------------------------------------------------------------------------
extern "C" void kernel_launch(void* const* d_in, const int* in_sizes, int n_in,
                              void* d_out, int out_size)
{
    const int*   x    = (const int*)  d_in[0];
    const float* Wih0 = (const float*)d_in[1];
    const float* Whh0 = (const float*)d_in[2];
    const float* bih0 = (const float*)d_in[3];
    const float* bhh0 = (const float*)d_in[4];
    const float* Wih1 = (const float*)d_in[5];
    const float* Whh1 = (const float*)d_in[6];
    const float* bih1 = (const float*)d_in[7];
    const float* bhh1 = (const float*)d_in[8];
    const float* fcW  = (const float*)d_in[9];
    const float* fcb  = (const float*)d_in[10];
    float* out = (float*)d_out;

    transpose_k<<<dim3(V_ / 32, H_ / 32, 2), dim3(32, 8)>>>(Wih0);
    gather_k<<<BT_, 256>>>(x, bih0, bhh0);
    rnn_layer_k<<<128, 256>>>(Whh0);
    gemm_k<<<dim3(8, BT_ / 128), 256>>>(Wih1, bih1, bhh1, nullptr, 1);
    rnn_layer_k<<<128, 256>>>(Whh1);
    gemm_k<<<dim3(8, BT_ / 128), 256>>>(fcW, fcb, nullptr, out, 0);
}

// round 6
// speedup vs baseline: 1.3100x; 1.0475x over previous
#include <cuda_runtime.h>

// ---------------------------------------------------------------------------
// SimpleRNN: 2-layer bidirectional tanh RNN + FC head.  B=32,T=2048,H=512.
//  - recurrence: Whh register-resident, fma.f32x2; h broadcast across 8-CTA
//    cluster via cp.async.bulk (8 x 512B per substep) + mbarrier complete_tx;
//    2 independent batch-pair pipelines hide DSMEM latency under compute.
//  - GEMMs: 128x128x16 tiles, f32x2 packed FMA along M, 2 CTAs/SM.
// ---------------------------------------------------------------------------

#define B_   32
#define T_   2048
#define H_   512
#define V_   8192
#define BT_  (B_ * T_)     // 65536
#define NW_  1024          // 2*H

__device__ float g_WihT[2 * V_ * H_];     //  33.5 MB
__device__ float g_pre [67108864];        // 268 MB  [BT][1024]
__device__ float g_hcat[67108864];        // 268 MB  [BT][1024]

// ---------------------------------------------------------------------------
// 1) Transpose Wih0 [2][H][V] -> g_WihT [2][V][H]
// ---------------------------------------------------------------------------
__global__ void transpose_k(const float* __restrict__ Wih0)
{
    __shared__ float tile[32][33];
    int d  = blockIdx.z;
    const float* S = Wih0   + (size_t)d * H_ * V_;
    float*       D = g_WihT + (size_t)d * V_ * H_;
    int v0 = blockIdx.x * 32;
    int h0 = blockIdx.y * 32;
    int tx = threadIdx.x, ty = threadIdx.y;
#pragma unroll
    for (int i = 0; i < 4; i++)
        tile[ty + 8 * i][tx] = S[(size_t)(h0 + ty + 8 * i) * V_ + v0 + tx];
    __syncthreads();
#pragma unroll
    for (int i = 0; i < 4; i++)
        D[(size_t)(v0 + ty + 8 * i) * H_ + h0 + tx] = tile[tx][ty + 8 * i];
}

// ---------------------------------------------------------------------------
// 2) Gather + biases -> g_pre
// ---------------------------------------------------------------------------
__global__ void gather_k(const int* __restrict__ x,
                         const float* __restrict__ bih0,
                         const float* __restrict__ bhh0)
{
    int bt  = blockIdx.x;
    int idx = __ldg(&x[bt]);
    int o   = threadIdx.x * 4;
    int dir = o >> 9;
    int h   = o & 511;
    float4 w  = *(const float4*)&g_WihT[((size_t)dir * V_ + idx) * H_ + h];
    float4 b1 = *(const float4*)&bih0[o];
    float4 b2 = *(const float4*)&bhh0[o];
    float4 r;
    r.x = w.x + b1.x + b2.x;
    r.y = w.y + b1.y + b2.y;
    r.z = w.z + b1.z + b2.z;
    r.w = w.w + b1.w + b2.w;
    *(float4*)&g_pre[(size_t)bt * NW_ + o] = r;
}

// ---------------------------------------------------------------------------
// 3/5) Recurrence. 16 clusters x 8 CTAs. CTA rank owns 64 Whh rows in REGS.
// Two batch-pair groups g={0,1}, each with double-buffered h + mbarriers.
// h-buffer layout per (g,buf): [owner 0..7][132 floats] where the owner block
// holds [2 batches][64 rows] (owner stride 132: 16B-aligned, bank-staggered).
// Broadcast: stage 128 floats locally, 8x cp.async.bulk 512B -> peers' buf,
// mbarrier expect_tx=4096.
// ---------------------------------------------------------------------------
#define FMA2(d, a, b) \
    asm("fma.rn.f32x2 %0, %1, %2, %0;" : "+l"(d) : "l"(a), "l"(b))

__global__ void __cluster_dims__(8, 1, 1) __launch_bounds__(256, 1)
rnn_layer_k(const float* __restrict__ Whh)
{
    __shared__ __align__(16) float s_h[2][2][1056];     // [g][buf][8*132]
    __shared__ __align__(16) float s_stage[2][2][128];  // [g][buf][2*64]
    __shared__ __align__(8)  unsigned long long s_mbar[4];  // [g*2+buf]

    int tid  = threadIdx.x;
    int rank = blockIdx.x & 7;
    int cid  = blockIdx.x >> 3;
    int dir  = cid >> 3;
    int b0   = (cid & 7) * 4;

    int kq   = tid & 3;                  // k-chunk 0..3 (lane bits 0-1)
    int r    = tid >> 2;                 // 0..63
    int grow = rank * 64 + r;
    int colbase = dir * H_ + grow;

    // --- my 128-float Whh chunk in registers (64 packed u64) ---
    unsigned long long wp[64];
    const unsigned long long* Wrow = (const unsigned long long*)
        (Whh + ((size_t)dir * H_ + grow) * H_ + kq * 128);
#pragma unroll
    for (int i = 0; i < 64; i++) wp[i] = Wrow[i];

    // --- zero h buffers, init mbarriers + prologue expects ---
    for (int i = tid; i < 2 * 2 * 1056; i += 256) ((float*)s_h)[i] = 0.0f;
    unsigned int hbase = (unsigned int)__cvta_generic_to_shared(&s_h[0][0][0]);
    unsigned int sbase = (unsigned int)__cvta_generic_to_shared(&s_stage[0][0][0]);
    unsigned int mbase = (unsigned int)__cvta_generic_to_shared(&s_mbar[0]);
    if (tid == 0) {
#pragma unroll
        for (int i = 0; i < 4; i++)
            asm volatile("mbarrier.init.shared.b64 [%0], %1;"
                         :: "r"(mbase + i * 8), "r"(1) : "memory");
        // first uses: buf1 at t=1, buf0 at t=2 (both groups)
#pragma unroll
        for (int i = 0; i < 4; i++)
            asm volatile("mbarrier.arrive.expect_tx.shared.b64 _, [%0], %1;"
                         :: "r"(mbase + i * 8), "r"(4096) : "memory");
    }
    __syncthreads();
    asm volatile("barrier.cluster.arrive.aligned;" ::: "memory");
    asm volatile("barrier.cluster.wait.aligned;" ::: "memory");

    unsigned int peer[8];
    unsigned int mdelta = mbase - hbase;
#pragma unroll
    for (int p = 0; p < 8; p++)
        asm volatile("mapa.shared::cluster.u32 %0, %1, %2;"
                     : "=r"(peer[p]) : "r"(hbase), "r"(p));

    // pv prefetch (lanes kq<2 own batch b0+2g+kq)
    float pv[2] = {0.0f, 0.0f};
    if (kq < 2) {
#pragma unroll
        for (int g = 0; g < 2; g++)
            pv[g] = __ldg(&g_pre[(((size_t)(b0 + 2 * g + kq) * T_ +
                                   (dir ? (T_ - 1) : 0)) << 10) + colbase]);
    }

    for (int t = 0; t < T_; t++) {
        int b   = t & 1;
        int par = (((t + 1) >> 1) - 1) & 1;
#pragma unroll
        for (int g = 0; g < 2; g++) {
            unsigned int mb = mbase + (unsigned)((g * 2 + b) * 8);

            // 1) wait for this buffer's data (t=0 reads zero-init, no wait)
            if (t > 0) {
                unsigned int done;
                asm volatile(
                    "{\n\t.reg .pred p;\n\t"
                    "mbarrier.try_wait.parity.acquire.cta.shared::cta.b64 p, [%1], %2;\n\t"
                    "selp.b32 %0, 1, 0, p;\n\t}"
                    : "=r"(done) : "r"(mb), "r"((unsigned)par) : "memory");
                if (!done) {
                    asm volatile(
                        "{\n\t.reg .pred P1;\n\t"
                        "WL_%=:\n\t"
                        "mbarrier.try_wait.parity.acquire.cta.shared::cta.b64 P1, [%0], %1, 0x989680;\n\t"
                        "@P1 bra.uni WD_%=;\n\t"
                        "bra.uni WL_%=;\n\t"
                        "WD_%=:\n\t}"
                        :: "r"(mb), "r"((unsigned)par) : "memory");
                }
            }
            // 2) re-arm this barrier for its next use (t+2), once prior phase done
            if (tid == 0 && t >= 1 && t + 2 <= T_ - 1)
                asm volatile("mbarrier.arrive.expect_tx.shared.b64 _, [%0], %1;"
                             :: "r"(mb), "r"(4096) : "memory");

            // 3) partial dots: owners 2kq, 2kq+1; batches 2g, 2g+1
            const ulonglong2* hp = (const ulonglong2*)&s_h[g][b][0];
            unsigned long long a0 = 0ULL, a1 = 0ULL;
#pragma unroll
            for (int o = 0; o < 2; o++) {
                int ob = (2 * kq + o) * 33;      // owner block, 16B units
#pragma unroll
                for (int j = 0; j < 16; j++) {
                    ulonglong2 h0 = hp[ob + j];       // batch-local 0
                    ulonglong2 h1 = hp[ob + 16 + j];  // batch-local 1
                    int wi = o * 32 + 2 * j;
                    FMA2(a0, wp[wi], h0.x); FMA2(a0, wp[wi + 1], h0.y);
                    FMA2(a1, wp[wi], h1.x); FMA2(a1, wp[wi + 1], h1.y);
                }
            }
            float s0, s1;
            {
                float lo, hi;
                asm("mov.b64 {%0, %1}, %2;" : "=f"(lo), "=f"(hi) : "l"(a0)); s0 = lo + hi;
                asm("mov.b64 {%0, %1}, %2;" : "=f"(lo), "=f"(hi) : "l"(a1)); s1 = lo + hi;
            }
            s0 += __shfl_xor_sync(0xffffffffu, s0, 1);
            s1 += __shfl_xor_sync(0xffffffffu, s1, 1);
            s0 += __shfl_xor_sync(0xffffffffu, s0, 2);
            s1 += __shfl_xor_sync(0xffffffffu, s1, 2);
            float sel = (kq & 1) ? s1 : s0;
            float hn  = tanhf(pv[g] + sel);

            // 4) output + staging (lanes kq<2 own a batch)
            if (kq < 2) {
                int tt = dir ? (T_ - 1 - t) : t;
                size_t batch = (size_t)(b0 + 2 * g + kq);
                g_hcat[((batch * T_ + tt) << 10) + colbase] = hn;
                s_stage[g][b][kq * 64 + r] = hn;
                if (t < T_ - 1) {
                    int tn = dir ? (T_ - 2 - t) : (t + 1);
                    pv[g] = __ldg(&g_pre[((batch * T_ + tn) << 10) + colbase]);
                }
            }

            // 5) staging visible + all reads of buf b complete
            __syncthreads();

            // 6) broadcast my 512B chunk to all 8 CTAs' buf b^1
            if (tid == 0 && t < T_ - 1) {
                asm volatile("fence.proxy.async.shared::cta;" ::: "memory");
                unsigned int src  = sbase + (unsigned)((g * 2 + b) * 512);
                unsigned int doff = (unsigned)(((g * 2 + (b ^ 1)) * 1056 + rank * 132) * 4);
                unsigned int moff = mdelta + (unsigned)((g * 2 + (b ^ 1)) * 8);
#pragma unroll
                for (int p = 0; p < 8; p++) {
                    asm volatile(
                        "cp.async.bulk.shared::cluster.shared::cta.mbarrier::complete_tx::bytes "
                        "[%0], [%1], %2, [%3];"
                        :: "r"(peer[p] + doff), "r"(src), "r"(512),
                           "r"(peer[p] + moff) : "memory");
                }
            }
        }
    }
    asm volatile("barrier.cluster.arrive.aligned;" ::: "memory");
    asm volatile("barrier.cluster.wait.aligned;" ::: "memory");
}

// ---------------------------------------------------------------------------
// 4/6) C[m][n] = sum_k g_hcat[m][k] * Bw[n][k] + bias1[n] (+ bias2[n])
// M=65536, N=1024, K=1024. BM=128, BN=128, BK=16, 256 thr, 8x8 microtile,
// f32x2 packed along M. Stride 136 (conflict-free STS), 2 CTAs/SM.
// ---------------------------------------------------------------------------
__global__ __launch_bounds__(256, 2)
void gemm_k(const float* __restrict__ Bw,
            const float* __restrict__ bias1,
            const float* __restrict__ bias2,
            float* __restrict__ Cext,
            int use_pre)
{
    __shared__ __align__(16) float As[16 * 136];   // [k][m]
    __shared__ __align__(16) float Bs[16 * 136];   // [k][n]

    float* C = use_pre ? g_pre : Cext;
    int m0 = blockIdx.y * 128;
    int n0 = blockIdx.x * 128;
    int tid = threadIdx.x;
    int tx = tid & 15;               // n-group: cols n0 + tx*8 .. +8
    int ty = tid >> 4;               // m-group: rows m0 + ty*8 .. +8

    unsigned long long acc[4][8];
#pragma unroll
    for (int i = 0; i < 4; i++)
#pragma unroll
        for (int j = 0; j < 8; j++) acc[i][j] = 0ULL;

    for (int kt = 0; kt < 1024; kt += 16) {
#pragma unroll
        for (int i = 0; i < 2; i++) {
            int j  = tid + 256 * i;
            int m  = j >> 2, kk = j & 3;
            float4 va = *(const float4*)&g_hcat[(size_t)(m0 + m) * 1024 + kt + kk * 4];
            As[(kk * 4 + 0) * 136 + m] = va.x;
            As[(kk * 4 + 1) * 136 + m] = va.y;
            As[(kk * 4 + 2) * 136 + m] = va.z;
            As[(kk * 4 + 3) * 136 + m] = va.w;
            float4 vb = *(const float4*)&Bw[(size_t)(n0 + m) * 1024 + kt + kk * 4];
            Bs[(kk * 4 + 0) * 136 + m] = vb.x;
            Bs[(kk * 4 + 1) * 136 + m] = vb.y;
            Bs[(kk * 4 + 2) * 136 + m] = vb.z;
            Bs[(kk * 4 + 3) * 136 + m] = vb.w;
        }
        __syncthreads();

#pragma unroll
        for (int k = 0; k < 16; k++) {
            const ulonglong2* ap = (const ulonglong2*)(As + k * 136 + ty * 8);
            ulonglong2 av0 = ap[0], av1 = ap[1];
            unsigned long long a[4] = {av0.x, av0.y, av1.x, av1.y};
            float4 bv0 = *(const float4*)(Bs + k * 136 + tx * 8);
            float4 bv1 = *(const float4*)(Bs + k * 136 + tx * 8 + 4);
            unsigned long long b[8];
            asm("mov.b64 %0, {%1, %1};" : "=l"(b[0]) : "f"(bv0.x));
            asm("mov.b64 %0, {%1, %1};" : "=l"(b[1]) : "f"(bv0.y));
            asm("mov.b64 %0, {%1, %1};" : "=l"(b[2]) : "f"(bv0.z));
            asm("mov.b64 %0, {%1, %1};" : "=l"(b[3]) : "f"(bv0.w));
            asm("mov.b64 %0, {%1, %1};" : "=l"(b[4]) : "f"(bv1.x));
            asm("mov.b64 %0, {%1, %1};" : "=l"(b[5]) : "f"(bv1.y));
            asm("mov.b64 %0, {%1, %1};" : "=l"(b[6]) : "f"(bv1.z));
            asm("mov.b64 %0, {%1, %1};" : "=l"(b[7]) : "f"(bv1.w));
#pragma unroll
            for (int i = 0; i < 4; i++)
#pragma unroll
                for (int j = 0; j < 8; j++)
                    FMA2(acc[i][j], a[i], b[j]);
        }
        __syncthreads();
    }

    float bs[8];
#pragma unroll
    for (int j = 0; j < 8; j++) {
        int n = n0 + tx * 8 + j;
        bs[j] = bias1[n] + (bias2 ? bias2[n] : 0.0f);
    }
#pragma unroll
    for (int i = 0; i < 4; i++) {
        float lo[8], hi[8];
#pragma unroll
        for (int j = 0; j < 8; j++) {
            float l, h;
            asm("mov.b64 {%0, %1}, %2;" : "=f"(l), "=f"(h) : "l"(acc[i][j]));
            lo[j] = l; hi[j] = h;
        }
        size_t row0 = (size_t)(m0 + ty * 8 + 2 * i) * 1024 + n0 + tx * 8;
        float4 r0, r1, r2, r3;
        r0.x = lo[0] + bs[0]; r0.y = lo[1] + bs[1]; r0.z = lo[2] + bs[2]; r0.w = lo[3] + bs[3];
        r1.x = lo[4] + bs[4]; r1.y = lo[5] + bs[5]; r1.z = lo[6] + bs[6]; r1.w = lo[7] + bs[7];
        r2.x = hi[0] + bs[0]; r2.y = hi[1] + bs[1]; r2.z = hi[2] + bs[2]; r2.w = hi[3] + bs[3];
        r3.x = hi[4] + bs[4]; r3.y = hi[5] + bs[5]; r3.z = hi[6] + bs[6]; r3.w = hi[7] + bs[7];
        *(float4*)&C[row0]            = r0;
        *(float4*)&C[row0 + 4]        = r1;
        *(float4*)&C[row0 + 1024]     = r2;
        *(float4*)&C[row0 + 1024 + 4] = r3;
    }
}

// ---------------------------------------------------------------------------
extern "C" void kernel_launch(void* const* d_in, const int* in_sizes, int n_in,
                              void* d_out, int out_size)
{
    const int*   x    = (const int*)  d_in[0];
    const float* Wih0 = (const float*)d_in[1];
    const float* Whh0 = (const float*)d_in[2];
    const float* bih0 = (const float*)d_in[3];
    const float* bhh0 = (const float*)d_in[4];
    const float* Wih1 = (const float*)d_in[5];
    const float* Whh1 = (const float*)d_in[6];
    const float* bih1 = (const float*)d_in[7];
    const float* bhh1 = (const float*)d_in[8];
    const float* fcW  = (const float*)d_in[9];
    const float* fcb  = (const float*)d_in[10];
    float* out = (float*)d_out;

    transpose_k<<<dim3(V_ / 32, H_ / 32, 2), dim3(32, 8)>>>(Wih0);
    gather_k<<<BT_, 256>>>(x, bih0, bhh0);
    rnn_layer_k<<<128, 256>>>(Whh0);
    gemm_k<<<dim3(8, BT_ / 128), 256>>>(Wih1, bih1, bhh1, nullptr, 1);
    rnn_layer_k<<<128, 256>>>(Whh1);
    gemm_k<<<dim3(8, BT_ / 128), 256>>>(fcW, fcb, nullptr, out, 0);
}